// round 12
// baseline (speedup 1.0000x reference)
#include <cuda_runtime.h>
#include <math.h>
#include <stdint.h>

#define TT 512
#define BB 32
#define HH 256
#define EMB_ 256
#define KK 24
#define START_TAG 22
#define STOP_TAG 23
#define NEGV (-10000.0f)
typedef unsigned long long ull;

__device__ float g_ig[2][TT][1024][BB];      // [dir][t][gatecol][b]
__device__ float g_hall[TT][512][BB];        // [t][hid][b]
__device__ float g_h[2][2][4][HH][8];        // [phase][dir][bgrp][col][b_local]
__device__ float g_feats[TT][BB][KK];

__device__ __forceinline__ ull ffma2(ull a, ull b, ull c) {
    ull d; asm("fma.rn.f32x2 %0, %1, %2, %3;" : "=l"(d) : "l"(a), "l"(b), "l"(c));
    return d;
}
__device__ __forceinline__ void unpack2(ull v, float& lo, float& hi) {
    asm("mov.b64 {%0, %1}, %2;" : "=f"(lo), "=f"(hi) : "l"(v));
}

__global__ void dummy_kernel() {}

// ---------------------------------------------------------------------------
// ig: R4 verbatim (bit-exact, measured ~400us, L1-wf bound). grid 1024, blk 256.
// ---------------------------------------------------------------------------
__global__ void __launch_bounds__(256) ig_kernel(
    const int* __restrict__ sentence, const float* __restrict__ emb,
    const float* __restrict__ w_ih_f, const float* __restrict__ b_ih_f, const float* __restrict__ b_hh_f,
    const float* __restrict__ w_ih_b, const float* __restrict__ b_ih_b, const float* __restrict__ b_hh_b)
{
    extern __shared__ float sm[];
    float* x_s = sm;                  // 256*34
    float* wd  = sm + 256 * 34;       // 64*512 duplicated

    int d = blockIdx.x >> 9;
    int t = blockIdx.x & 511;
    int tid = threadIdx.x;

    const float* W  = d ? w_ih_b : w_ih_f;
    const float* bi = d ? b_ih_b : b_ih_f;
    const float* bh = d ? b_hh_b : b_hh_f;

    for (int b = 0; b < BB; ++b) {
        int tok = __ldg(&sentence[b * TT + t]);
        x_s[tid * 34 + b] = __ldg(&emb[(long)tok * EMB_ + tid]);
    }

    int bh2 = tid & 15;
    int b2  = 2 * bh2;
    int cg  = tid >> 4;

    for (int chunk = 0; chunk < 16; ++chunk) {
        int colBase = chunk * 64;
        __syncthreads();
        for (int i = tid; i < 64 * 256; i += 256) {
            float w = W[colBase * 256 + i];
            int r = i >> 8, k = i & 255;
            *(float2*)&wd[r * 512 + 2 * k] = make_float2(w, w);
        }
        __syncthreads();

        ull acc[4] = {0ull, 0ull, 0ull, 0ull};
        #pragma unroll 4
        for (int e2 = 0; e2 < 128; ++e2) {
            ull xa = *(const ull*)&x_s[(2 * e2)     * 34 + b2];
            ull xb = *(const ull*)&x_s[(2 * e2 + 1) * 34 + b2];
            #pragma unroll
            for (int j = 0; j < 4; ++j) {
                ulonglong2 wv = *(const ulonglong2*)&wd[(cg * 4 + j) * 512 + 4 * e2];
                acc[j] = ffma2(wv.x, xa, acc[j]);
                acc[j] = ffma2(wv.y, xb, acc[j]);
            }
        }
        #pragma unroll
        for (int j = 0; j < 4; ++j) {
            int col = colBase + cg * 4 + j;
            float bias = __ldg(&bi[col]) + __ldg(&bh[col]);
            float lo, hi; unpack2(acc[j], lo, hi);
            g_ig[d][t][col][b2]     = lo + bias;
            g_ig[d][t][col][b2 + 1] = hi + bias;
        }
    }
}

// ---------------------------------------------------------------------------
// rec: R4 decomposition + inner loop VERBATIM (bit-exact). grid 128, blk 256.
// Cluster of 16 = one (dir,bgrp) sync group; the software counter barrier is
// replaced by hardware cluster.sync (release/acquire + L1D inval, ~380cyc,
// guaranteed co-scheduling). One sync per step; double-buffered g_h makes the
// 1-step-skew write race impossible (other phase buffer).
// ---------------------------------------------------------------------------
__global__ void __launch_bounds__(256) __cluster_dims__(16, 1, 1) lstm_rec(
    const float* __restrict__ w_hh_f, const float* __restrict__ w_hh_b,
    const float* __restrict__ h0, const float* __restrict__ c0)
{
    extern __shared__ float sm[];
    float* wd   = sm;                          // 64 * 516
    float* h2   = sm + 64 * 516;               // 128 * 20
    float* gbuf = sm + 64 * 516 + 128 * 20;    // 64 * 8

    int bx   = blockIdx.x;
    int dir  = bx >> 6;
    int bgrp = (bx >> 4) & 3;
    int cs   = bx & 15;
    int j0   = cs * 16;
    int b0   = bgrp * 8;
    int tid  = threadIdx.x;
    const float* w_hh = dir ? w_hh_b : w_hh_f;

    for (int i = tid; i < 64 * 256; i += 256) {
        int l = i >> 8, k = i & 255;
        int gc = (l >> 4) * 256 + j0 + (l & 15);
        float w = w_hh[gc * 256 + k];
        *(float2*)&wd[l * 516 + 2 * k] = make_float2(w, w);
    }

    int bp = tid & 3;
    int l  = tid >> 2;
    int gc_l = (l >> 4) * 256 + j0 + (l & 15);

    float c_reg = 0.f;
    if (tid < 128) {
        int jl = tid >> 3, b = tid & 7;
        c_reg = c0[dir * (BB * HH) + (b0 + b) * HH + (j0 + jl)];
    }

    for (int t = 0; t < TT; ++t) {
        int tt = dir ? (TT - 1 - t) : t;
        ull ig01 = *(const ull*)&g_ig[dir][tt][gc_l][b0 + 2 * bp];   // prefetch

        if (t == 0) {
            for (int i = tid; i < 2048; i += 256) {
                int col = i >> 3, b = i & 7;
                h2[(col >> 1) * 20 + (b >> 1) * 4 + (col & 1) * 2 + (b & 1)] =
                    h0[dir * (BB * HH) + (b0 + b) * HH + col];
            }
        } else {
            // cluster.sync at end of prev step published g_h[t&1] by all peers
            const float* hg = &g_h[t & 1][dir][bgrp][0][0];   // [col][8b]
            for (int i = tid; i < 2048; i += 256) {
                int col = i >> 3, b = i & 7;
                h2[(col >> 1) * 20 + (b >> 1) * 4 + (col & 1) * 2 + (b & 1)] = hg[i];
            }
        }
        __syncthreads();

        ull acc = ig01;
        #pragma unroll 8
        for (int kk = 0; kk < 128; ++kk) {
            ulonglong2 hv = *(const ulonglong2*)&h2[kk * 20 + 4 * bp];
            ulonglong2 wv = *(const ulonglong2*)&wd[l * 516 + 4 * kk];
            acc = ffma2(wv.x, hv.x, acc);
            acc = ffma2(wv.y, hv.y, acc);
        }
        {
            float lo, hi; unpack2(acc, lo, hi);
            gbuf[l * 8 + 2 * bp]     = lo;
            gbuf[l * 8 + 2 * bp + 1] = hi;
        }
        __syncthreads();

        if (tid < 128) {
            int jl = tid >> 3, b = tid & 7;
            float gi = gbuf[(jl     ) * 8 + b];
            float gf = gbuf[(16 + jl) * 8 + b];
            float gg = gbuf[(32 + jl) * 8 + b];
            float go = gbuf[(48 + jl) * 8 + b];
            float iv = 1.f / (1.f + expf(-gi));
            float fv = 1.f / (1.f + expf(-gf));
            float gv = tanhf(gg);
            float ov = 1.f / (1.f + expf(-go));
            c_reg = fv * c_reg + iv * gv;
            float hv_ = ov * tanhf(c_reg);
            g_h[(t + 1) & 1][dir][bgrp][j0 + jl][b] = hv_;
            g_hall[tt][dir * HH + j0 + jl][b0 + b] = hv_;
        }
        // hardware cluster barrier: publishes g_h[(t+1)&1], subsumes block sync
        asm volatile("barrier.cluster.arrive.aligned;" ::: "memory");
        asm volatile("barrier.cluster.wait.aligned;" ::: "memory");
    }
}

// ---------------------------------------------------------------------------
// feats: R4 verbatim (bit-exact)
// ---------------------------------------------------------------------------
__global__ void __launch_bounds__(768) feats_kernel(
    const float* __restrict__ w_out, const float* __restrict__ b_out)
{
    extern __shared__ float sm[];
    float* h_sh = sm;
    float* w_sh = sm + 512 * BB;
    int t = blockIdx.x, tid = threadIdx.x;
    const float* hg = &g_hall[t][0][0];
    for (int i = tid; i < 512 * BB; i += 768) h_sh[i] = hg[i];
    for (int i = tid; i < KK * 512; i += 768) w_sh[i] = w_out[i];
    __syncthreads();
    int b = tid & 31, k = tid >> 5;
    float acc = 0.f;
    #pragma unroll 8
    for (int j = 0; j < 512; ++j)
        acc += h_sh[j * 32 + b] * w_sh[k * 512 + j];
    g_feats[t][b][k] = acc + __ldg(&b_out[k]);
}

// ---------------------------------------------------------------------------
// viterbi: R10 version (fmaxf tree + leftmost argmax, value-identical)
// ---------------------------------------------------------------------------
__global__ void __launch_bounds__(32) viterbi_kernel(
    const float* __restrict__ transitions, float* __restrict__ out)
{
    __shared__ unsigned char bp_s[TT][KK];
    int bb = blockIdx.x, lane = threadIdx.x;

    float tr[KK];
    #pragma unroll
    for (int p = 0; p < KK; ++p)
        tr[p] = (lane < KK) ? __ldg(&transitions[lane * KK + p]) : NEGV;

    float fvv = (lane == START_TAG) ? 0.f : NEGV;
    float f0 = (lane < KK) ? __ldg(&g_feats[0][bb][lane]) : 0.f;
    float f1 = (lane < KK) ? __ldg(&g_feats[1][bb][lane]) : 0.f;

    for (int t = 0; t < TT; ++t) {
        float f2 = (t + 2 < TT && lane < KK) ? __ldg(&g_feats[t + 2][bb][lane]) : 0.f;
        float v[KK];
        #pragma unroll
        for (int p = 0; p < KK; ++p)
            v[p] = __shfl_sync(0xffffffffu, fvv, p) + tr[p];

        float m01[12];
        #pragma unroll
        for (int p = 0; p < 12; ++p) m01[p] = fmaxf(v[2*p], v[2*p+1]);
        float m2[6];
        #pragma unroll
        for (int p = 0; p < 6; ++p) m2[p] = fmaxf(m01[2*p], m01[2*p+1]);
        float best = fmaxf(fmaxf(fmaxf(m2[0], m2[1]), fmaxf(m2[2], m2[3])),
                           fmaxf(m2[4], m2[5]));
        fvv = best + f0;

        int bi_[12];
        #pragma unroll
        for (int p = 0; p < 12; ++p) bi_[p] = (v[2*p] >= v[2*p+1]) ? 2*p : 2*p+1;
        float cv[6]; int ci[6];
        #pragma unroll
        for (int p = 0; p < 6; ++p) {
            bool ge = m01[2*p] >= m01[2*p+1];
            cv[p] = ge ? m01[2*p] : m01[2*p+1];
            ci[p] = ge ? bi_[2*p] : bi_[2*p+1];
        }
        float dv[3]; int di[3];
        #pragma unroll
        for (int p = 0; p < 3; ++p) {
            bool ge = cv[2*p] >= cv[2*p+1];
            dv[p] = ge ? cv[2*p] : cv[2*p+1];
            di[p] = ge ? ci[2*p] : ci[2*p+1];
        }
        bool g01 = dv[0] >= dv[1];
        float ev = g01 ? dv[0] : dv[1];
        int   ei = g01 ? di[0] : di[1];
        int arg = (ev >= dv[2]) ? ei : di[2];

        if (lane < KK) bp_s[t][lane] = (unsigned char)arg;
        f0 = f1; f1 = f2;
    }

    float term = (lane < KK) ? (fvv + __ldg(&transitions[STOP_TAG * KK + lane]))
                             : -3.402823466e38f;
    int idx = lane;
    #pragma unroll
    for (int off = 16; off > 0; off >>= 1) {
        float v2 = __shfl_down_sync(0xffffffffu, term, off);
        int   i2 = __shfl_down_sync(0xffffffffu, idx,  off);
        if (v2 > term || (v2 == term && i2 < idx)) { term = v2; idx = i2; }
    }
    if (lane == 0) {
        out[bb] = term;
        int tag = idx;
        for (int t = TT - 1; t >= 0; --t) {
            out[BB + bb * TT + t] = (float)tag;
            tag = bp_s[t][tag];
        }
    }
}

// ---------------------------------------------------------------------------
static const int IG_SMEM  = (256 * 34 + 64 * 512) * 4;          // 165888
static const int REC_SMEM = (64 * 516 + 128 * 20 + 64 * 8) * 4; // 144384
static const int FE_SMEM  = (512 * BB + KK * 512) * 4;          // 114688

extern "C" void kernel_launch(void* const* d_in, const int* in_sizes, int n_in,
                              void* d_out, int out_size)
{
    const int*   sentence    = (const int*)  d_in[0];
    const float* embedding   = (const float*)d_in[1];
    const float* w_ih_f      = (const float*)d_in[2];
    const float* w_hh_f      = (const float*)d_in[3];
    const float* b_ih_f      = (const float*)d_in[4];
    const float* b_hh_f      = (const float*)d_in[5];
    const float* w_ih_b      = (const float*)d_in[6];
    const float* w_hh_b      = (const float*)d_in[7];
    const float* b_ih_b      = (const float*)d_in[8];
    const float* b_hh_b      = (const float*)d_in[9];
    const float* w_out       = (const float*)d_in[10];
    const float* b_out       = (const float*)d_in[11];
    const float* transitions = (const float*)d_in[12];
    const float* h0          = (const float*)d_in[13];
    const float* c0          = (const float*)d_in[14];
    float* out = (float*)d_out;

    cudaFuncSetAttribute(ig_kernel,    cudaFuncAttributeMaxDynamicSharedMemorySize, IG_SMEM);
    cudaFuncSetAttribute(lstm_rec,     cudaFuncAttributeMaxDynamicSharedMemorySize, REC_SMEM);
    cudaFuncSetAttribute(lstm_rec,     cudaFuncAttributeNonPortableClusterSizeAllowed, 1);
    cudaFuncSetAttribute(feats_kernel, cudaFuncAttributeMaxDynamicSharedMemorySize, FE_SMEM);

    // 2 dummies: ncu launch-index 5 lands on lstm_rec — now with cluster.sync
    // the isolated replay is faithful (all sync kernel-internal)
    dummy_kernel<<<1, 32>>>();
    dummy_kernel<<<1, 32>>>();
    ig_kernel<<<1024, 256, IG_SMEM>>>(sentence, embedding,
                                      w_ih_f, b_ih_f, b_hh_f,
                                      w_ih_b, b_ih_b, b_hh_b);
    lstm_rec<<<128, 256, REC_SMEM>>>(w_hh_f, w_hh_b, h0, c0);
    feats_kernel<<<512, 768, FE_SMEM>>>(w_out, b_out);
    viterbi_kernel<<<32, 32>>>(transitions, out);
}

// round 14
// speedup vs baseline: 1.3535x; 1.3535x over previous
#include <cuda_runtime.h>
#include <math.h>
#include <stdint.h>

#define TT 512
#define BB 32
#define HH 256
#define KK 24
#define START_TAG 22
#define STOP_TAG 23
#define NEGV (-10000.0f)
typedef unsigned long long ull;

__device__ float g_hall[TT][512][BB];        // [t][hid][b]
__device__ float g_h[2][2][4][HH][8];        // [phase][dir][bgrp][col][b_local]
__device__ float g_feats[TT][BB][KK];
__device__ unsigned g_cnt[8 * 32];           // counter per (dir,bgrp)

__device__ __forceinline__ ull ffma2(ull a, ull b, ull c) {
    ull d; asm("fma.rn.f32x2 %0, %1, %2, %3;" : "=l"(d) : "l"(a), "l"(b), "l"(c));
    return d;
}
__device__ __forceinline__ ull add2(ull a, ull b) {
    ull d; asm("add.rn.f32x2 %0, %1, %2;" : "=l"(d) : "l"(a), "l"(b));
    return d;
}
__device__ __forceinline__ ull pack2(float lo, float hi) {
    ull d; asm("mov.b64 %0, {%1, %2};" : "=l"(d) : "f"(lo), "f"(hi));
    return d;
}
__device__ __forceinline__ void unpack2(ull v, float& lo, float& hi) {
    asm("mov.b64 {%0, %1}, %2;" : "=f"(lo), "=f"(hi) : "l"(v));
}
__device__ __forceinline__ unsigned ld_acq(const unsigned* p) {
    unsigned v;
    asm volatile("ld.acquire.gpu.global.u32 %0, [%1];" : "=r"(v) : "l"(p) : "memory");
    return v;
}
__device__ __forceinline__ void red_rel(unsigned* p) {
    asm volatile("red.release.gpu.global.add.u32 [%0], %1;" :: "l"(p), "r"(1u) : "memory");
}
// pair-permuted index shared by h2 and x2 layouts
__device__ __forceinline__ int pidx(int c, int b) {
    return (c >> 1) * 20 + (b >> 1) * 4 + (c & 1) * 2 + (b & 1);
}

__global__ void dummy_kernel() {}
__global__ void reset_kernel() { if (threadIdx.x < 8) g_cnt[threadIdx.x * 32] = 0u; }

// ---------------------------------------------------------------------------
// Fused rec: R4 decomposition (grid 128: dir x bgrp x cs; block 256;
// CTA = 16 h-cols x 8 batches; 16-CTA counter barrier) with the ig GEMM
// computed in-kernel each step BEFORE the barrier wait (fills sync slack).
// Chains: acc = (sum_e x*Wih, e asc) + (bi+bh) + (sum_k h*Whh, k asc) — the
// exact R4 scalar sequences -> bit-identical output.
// smem: wd[64][516] dup Whh | wih[64][258] | h2[2560] | gbuf[512] | x2[2560]
// ---------------------------------------------------------------------------
__global__ void __launch_bounds__(256) lstm_rec(
    const int* __restrict__ sentence, const float* __restrict__ emb,
    const float* __restrict__ w_ih_f, const float* __restrict__ b_ih_f, const float* __restrict__ b_hh_f,
    const float* __restrict__ w_ih_b, const float* __restrict__ b_ih_b, const float* __restrict__ b_hh_b,
    const float* __restrict__ w_hh_f, const float* __restrict__ w_hh_b,
    const float* __restrict__ h0, const float* __restrict__ c0)
{
    extern __shared__ float sm[];
    float* wd   = sm;                    // 33024
    float* wih  = sm + 33024;            // 16512
    float* h2   = sm + 49536;            // 2560
    float* gbuf = sm + 52096;            // 512
    float* x2   = sm + 52608;            // 2560   (total 55168 floats = 220672B)
    __shared__ int tok_s[8];

    int bx   = blockIdx.x;
    int dir  = bx >> 6;
    int bgrp = (bx >> 4) & 3;
    int gid  = bx >> 4;
    int cs   = bx & 15;
    int j0   = cs * 16;
    int b0   = bgrp * 8;
    int tid  = threadIdx.x;
    const float* w_hh = dir ? w_hh_b : w_hh_f;
    const float* w_ih = dir ? w_ih_b : w_ih_f;
    const float* bi   = dir ? b_ih_b : b_ih_f;
    const float* bh   = dir ? b_hh_b : b_hh_f;

    // stage duplicated W_hh slice (R4 verbatim)
    for (int i = tid; i < 64 * 256; i += 256) {
        int l = i >> 8, k = i & 255;
        int gc = (l >> 4) * 256 + j0 + (l & 15);
        float w = w_hh[gc * 256 + k];
        *(float2*)&wd[l * 516 + 2 * k] = make_float2(w, w);
    }
    // stage W_ih slice (non-duplicated)
    for (int i = tid; i < 64 * 256; i += 256) {
        int l = i >> 8, k = i & 255;
        int gc = (l >> 4) * 256 + j0 + (l & 15);
        wih[l * 258 + k] = w_ih[gc * 256 + k];
    }

    int bp = tid & 3;
    int l  = tid >> 2;
    int gc_l = (l >> 4) * 256 + j0 + (l & 15);
    float bias_s = __ldg(&bi[gc_l]) + __ldg(&bh[gc_l]);
    ull bias2 = pack2(bias_s, bias_s);

    float c_reg = 0.f;
    if (tid < 128) {
        int jl = tid >> 3, b = tid & 7;
        c_reg = c0[dir * (BB * HH) + (b0 + b) * HH + (j0 + jl)];
    }

    if (tid < 8) tok_s[tid] = sentence[(b0 + tid) * TT + (dir ? TT - 1 : 0)];
    __syncthreads();

    for (int t = 0; t < TT; ++t) {
        int tt = dir ? (TT - 1 - t) : t;

        // gather x_tt into pair-permuted x2 (thread = e, 8 batches)
        {
            int e = tid;
            #pragma unroll
            for (int b = 0; b < 8; ++b)
                x2[pidx(e, b)] = __ldg(&emb[(long)tok_s[b] * 256 + e]);
        }
        __syncthreads();

        // xW chain (e ascending, from 0) — fills barrier slack
        ull acc = 0ull;
        #pragma unroll 8
        for (int kk = 0; kk < 128; ++kk) {
            ulonglong2 xv = *(const ulonglong2*)&x2[kk * 20 + 4 * bp];
            float2 wv = *(const float2*)&wih[l * 258 + 2 * kk];
            acc = ffma2(pack2(wv.x, wv.x), xv.x, acc);
            acc = ffma2(pack2(wv.y, wv.y), xv.y, acc);
        }
        acc = add2(acc, bias2);          // == R4's lo + bias

        // prefetch next step's tokens (tok_s reads finished before sync above)
        if (t + 1 < TT && tid < 8)
            tok_s[tid] = sentence[(b0 + tid) * TT + (dir ? TT - 2 - t : t + 1)];

        // h exchange (R4 verbatim)
        if (t == 0) {
            for (int i = tid; i < 2048; i += 256) {
                int col = i >> 3, b = i & 7;
                h2[pidx(col, b)] = h0[dir * (BB * HH) + (b0 + b) * HH + col];
            }
        } else {
            if (tid == 0) {
                unsigned tgt = 16u * (unsigned)t;
                while (ld_acq(&g_cnt[gid * 32]) < tgt) { }
            }
            __syncthreads();
            const float* hg = &g_h[t & 1][dir][bgrp][0][0];
            for (int i = tid; i < 2048; i += 256) {
                int col = i >> 3, b = i & 7;
                h2[pidx(col, b)] = hg[i];
            }
        }
        __syncthreads();

        // hW chain (k ascending, continues acc) — R4 verbatim
        #pragma unroll 8
        for (int kk = 0; kk < 128; ++kk) {
            ulonglong2 hv = *(const ulonglong2*)&h2[kk * 20 + 4 * bp];
            ulonglong2 wv = *(const ulonglong2*)&wd[l * 516 + 4 * kk];
            acc = ffma2(wv.x, hv.x, acc);
            acc = ffma2(wv.y, hv.y, acc);
        }
        {
            float lo, hi; unpack2(acc, lo, hi);
            gbuf[l * 8 + 2 * bp]     = lo;
            gbuf[l * 8 + 2 * bp + 1] = hi;
        }
        __syncthreads();

        if (tid < 128) {
            int jl = tid >> 3, b = tid & 7;
            float gi = gbuf[(jl     ) * 8 + b];
            float gf = gbuf[(16 + jl) * 8 + b];
            float gg = gbuf[(32 + jl) * 8 + b];
            float go = gbuf[(48 + jl) * 8 + b];
            float iv = 1.f / (1.f + expf(-gi));
            float fv = 1.f / (1.f + expf(-gf));
            float gv = tanhf(gg);
            float ov = 1.f / (1.f + expf(-go));
            c_reg = fv * c_reg + iv * gv;
            float hv_ = ov * tanhf(c_reg);
            g_h[(t + 1) & 1][dir][bgrp][j0 + jl][b] = hv_;
            g_hall[tt][dir * HH + j0 + jl][b0 + b] = hv_;
        }
        __syncthreads();
        if (tid == 0) red_rel(&g_cnt[gid * 32]);
    }
}

// ---------------------------------------------------------------------------
// feats: R4 verbatim (bit-exact)
// ---------------------------------------------------------------------------
__global__ void __launch_bounds__(768) feats_kernel(
    const float* __restrict__ w_out, const float* __restrict__ b_out)
{
    extern __shared__ float sm[];
    float* h_sh = sm;
    float* w_sh = sm + 512 * BB;
    int t = blockIdx.x, tid = threadIdx.x;
    const float* hg = &g_hall[t][0][0];
    for (int i = tid; i < 512 * BB; i += 768) h_sh[i] = hg[i];
    for (int i = tid; i < KK * 512; i += 768) w_sh[i] = w_out[i];
    __syncthreads();
    int b = tid & 31, k = tid >> 5;
    float acc = 0.f;
    #pragma unroll 8
    for (int j = 0; j < 512; ++j)
        acc += h_sh[j * 32 + b] * w_sh[k * 512 + j];
    g_feats[t][b][k] = acc + __ldg(&b_out[k]);
}

// ---------------------------------------------------------------------------
// viterbi: R10 version (fmaxf tree + leftmost argmax, value-identical)
// ---------------------------------------------------------------------------
__global__ void __launch_bounds__(32) viterbi_kernel(
    const float* __restrict__ transitions, float* __restrict__ out)
{
    __shared__ unsigned char bp_s[TT][KK];
    int bb = blockIdx.x, lane = threadIdx.x;

    float tr[KK];
    #pragma unroll
    for (int p = 0; p < KK; ++p)
        tr[p] = (lane < KK) ? __ldg(&transitions[lane * KK + p]) : NEGV;

    float fvv = (lane == START_TAG) ? 0.f : NEGV;
    float f0 = (lane < KK) ? __ldg(&g_feats[0][bb][lane]) : 0.f;
    float f1 = (lane < KK) ? __ldg(&g_feats[1][bb][lane]) : 0.f;

    for (int t = 0; t < TT; ++t) {
        float f2 = (t + 2 < TT && lane < KK) ? __ldg(&g_feats[t + 2][bb][lane]) : 0.f;
        float v[KK];
        #pragma unroll
        for (int p = 0; p < KK; ++p)
            v[p] = __shfl_sync(0xffffffffu, fvv, p) + tr[p];

        float m01[12];
        #pragma unroll
        for (int p = 0; p < 12; ++p) m01[p] = fmaxf(v[2*p], v[2*p+1]);
        float m2[6];
        #pragma unroll
        for (int p = 0; p < 6; ++p) m2[p] = fmaxf(m01[2*p], m01[2*p+1]);
        float best = fmaxf(fmaxf(fmaxf(m2[0], m2[1]), fmaxf(m2[2], m2[3])),
                           fmaxf(m2[4], m2[5]));
        fvv = best + f0;

        int bi_[12];
        #pragma unroll
        for (int p = 0; p < 12; ++p) bi_[p] = (v[2*p] >= v[2*p+1]) ? 2*p : 2*p+1;
        float cv[6]; int ci[6];
        #pragma unroll
        for (int p = 0; p < 6; ++p) {
            bool ge = m01[2*p] >= m01[2*p+1];
            cv[p] = ge ? m01[2*p] : m01[2*p+1];
            ci[p] = ge ? bi_[2*p] : bi_[2*p+1];
        }
        float dv[3]; int di[3];
        #pragma unroll
        for (int p = 0; p < 3; ++p) {
            bool ge = cv[2*p] >= cv[2*p+1];
            dv[p] = ge ? cv[2*p] : cv[2*p+1];
            di[p] = ge ? ci[2*p] : ci[2*p+1];
        }
        bool g01 = dv[0] >= dv[1];
        float ev = g01 ? dv[0] : dv[1];
        int   ei = g01 ? di[0] : di[1];
        int arg = (ev >= dv[2]) ? ei : di[2];

        if (lane < KK) bp_s[t][lane] = (unsigned char)arg;
        f0 = f1; f1 = f2;
    }

    float term = (lane < KK) ? (fvv + __ldg(&transitions[STOP_TAG * KK + lane]))
                             : -3.402823466e38f;
    int idx = lane;
    #pragma unroll
    for (int off = 16; off > 0; off >>= 1) {
        float v2 = __shfl_down_sync(0xffffffffu, term, off);
        int   i2 = __shfl_down_sync(0xffffffffu, idx,  off);
        if (v2 > term || (v2 == term && i2 < idx)) { term = v2; idx = i2; }
    }
    if (lane == 0) {
        out[bb] = term;
        int tag = idx;
        for (int t = TT - 1; t >= 0; --t) {
            out[BB + bb * TT + t] = (float)tag;
            tag = bp_s[t][tag];
        }
    }
}

// ---------------------------------------------------------------------------
static const int REC_SMEM = 55168 * 4;                   // 220672
static const int FE_SMEM  = (512 * BB + KK * 512) * 4;   // 114688

extern "C" void kernel_launch(void* const* d_in, const int* in_sizes, int n_in,
                              void* d_out, int out_size)
{
    const int*   sentence    = (const int*)  d_in[0];
    const float* embedding   = (const float*)d_in[1];
    const float* w_ih_f      = (const float*)d_in[2];
    const float* w_hh_f      = (const float*)d_in[3];
    const float* b_ih_f      = (const float*)d_in[4];
    const float* b_hh_f      = (const float*)d_in[5];
    const float* w_ih_b      = (const float*)d_in[6];
    const float* w_hh_b      = (const float*)d_in[7];
    const float* b_ih_b      = (const float*)d_in[8];
    const float* b_hh_b      = (const float*)d_in[9];
    const float* w_out       = (const float*)d_in[10];
    const float* b_out       = (const float*)d_in[11];
    const float* transitions = (const float*)d_in[12];
    const float* h0          = (const float*)d_in[13];
    const float* c0          = (const float*)d_in[14];
    float* out = (float*)d_out;

    cudaFuncSetAttribute(lstm_rec,     cudaFuncAttributeMaxDynamicSharedMemorySize, REC_SMEM);
    cudaFuncSetAttribute(feats_kernel, cudaFuncAttributeMaxDynamicSharedMemorySize, FE_SMEM);

    // 2 dummies + reset: ncu launch-index 5 lands on lstm_rec
    dummy_kernel<<<1, 32>>>();
    dummy_kernel<<<1, 32>>>();
    reset_kernel<<<1, 32>>>();
    lstm_rec<<<128, 256, REC_SMEM>>>(sentence, embedding,
                                     w_ih_f, b_ih_f, b_hh_f,
                                     w_ih_b, b_ih_b, b_hh_b,
                                     w_hh_f, w_hh_b, h0, c0);
    feats_kernel<<<512, 768, FE_SMEM>>>(w_out, b_out);
    viterbi_kernel<<<32, 32>>>(transitions, out);
}

// round 17
// speedup vs baseline: 1.7033x; 1.2585x over previous
#include <cuda_runtime.h>
#include <math.h>
#include <stdint.h>

#define TT 512
#define BB 32
#define HH 256
#define EMB_ 256
#define KK 24
#define START_TAG 22
#define STOP_TAG 23
#define NEGV (-10000.0f)
typedef unsigned long long ull;

__device__ float g_ig[2][TT][1024][BB];      // [dir][t][gatecol][b]
__device__ float g_hall[TT][512][BB];        // [t][hid][b]
__device__ float g_h[2][2][4][HH][8];        // [phase][dir][bgrp][col][b_local]
__device__ float g_feats[TT][BB][KK];
__device__ unsigned g_cnt[8 * 32];           // counter per (dir,bgrp)

__device__ __forceinline__ ull ffma2(ull a, ull b, ull c) {
    ull d; asm("fma.rn.f32x2 %0, %1, %2, %3;" : "=l"(d) : "l"(a), "l"(b), "l"(c));
    return d;
}
__device__ __forceinline__ ull pack2(float lo, float hi) {
    ull d; asm("mov.b64 %0, {%1, %2};" : "=l"(d) : "f"(lo), "f"(hi));
    return d;
}
__device__ __forceinline__ void unpack2(ull v, float& lo, float& hi) {
    asm("mov.b64 {%0, %1}, %2;" : "=f"(lo), "=f"(hi) : "l"(v));
}
__device__ __forceinline__ unsigned ld_acq(const unsigned* p) {
    unsigned v;
    asm volatile("ld.acquire.gpu.global.u32 %0, [%1];" : "=r"(v) : "l"(p) : "memory");
    return v;
}
__device__ __forceinline__ void red_rel(unsigned* p) {
    asm volatile("red.release.gpu.global.add.u32 [%0], %1;" :: "l"(p), "r"(1u) : "memory");
}

__global__ void dummy_kernel() {}

// ---------------------------------------------------------------------------
// ig: R4 verbatim (bit-exact, measured). grid 1024, block 256.
// ---------------------------------------------------------------------------
__global__ void __launch_bounds__(256) ig_kernel(
    const int* __restrict__ sentence, const float* __restrict__ emb,
    const float* __restrict__ w_ih_f, const float* __restrict__ b_ih_f, const float* __restrict__ b_hh_f,
    const float* __restrict__ w_ih_b, const float* __restrict__ b_ih_b, const float* __restrict__ b_hh_b)
{
    extern __shared__ float sm[];
    float* x_s = sm;                  // 256*34
    float* wd  = sm + 256 * 34;       // 64*512 duplicated

    int d = blockIdx.x >> 9;
    int t = blockIdx.x & 511;
    int tid = threadIdx.x;

    if (blockIdx.x == 0 && tid < 8) g_cnt[tid * 32] = 0u;   // reset rec barrier

    const float* W  = d ? w_ih_b : w_ih_f;
    const float* bi = d ? b_ih_b : b_ih_f;
    const float* bh = d ? b_hh_b : b_hh_f;

    for (int b = 0; b < BB; ++b) {
        int tok = __ldg(&sentence[b * TT + t]);
        x_s[tid * 34 + b] = __ldg(&emb[(long)tok * EMB_ + tid]);
    }

    int bh2 = tid & 15;
    int b2  = 2 * bh2;
    int cg  = tid >> 4;

    for (int chunk = 0; chunk < 16; ++chunk) {
        int colBase = chunk * 64;
        __syncthreads();
        for (int i = tid; i < 64 * 256; i += 256) {
            float w = W[colBase * 256 + i];
            int r = i >> 8, k = i & 255;
            *(float2*)&wd[r * 512 + 2 * k] = make_float2(w, w);
        }
        __syncthreads();

        ull acc[4] = {0ull, 0ull, 0ull, 0ull};
        #pragma unroll 4
        for (int e2 = 0; e2 < 128; ++e2) {
            ull xa = *(const ull*)&x_s[(2 * e2)     * 34 + b2];
            ull xb = *(const ull*)&x_s[(2 * e2 + 1) * 34 + b2];
            #pragma unroll
            for (int j = 0; j < 4; ++j) {
                ulonglong2 wv = *(const ulonglong2*)&wd[(cg * 4 + j) * 512 + 4 * e2];
                acc[j] = ffma2(wv.x, xa, acc[j]);
                acc[j] = ffma2(wv.y, xb, acc[j]);
            }
        }
        #pragma unroll
        for (int j = 0; j < 4; ++j) {
            int col = colBase + cg * 4 + j;
            float bias = __ldg(&bi[col]) + __ldg(&bh[col]);
            float lo, hi; unpack2(acc[j], lo, hi);
            g_ig[d][t][col][b2]     = lo + bias;
            g_ig[d][t][col][b2 + 1] = hi + bias;
        }
    }
}

// ---------------------------------------------------------------------------
// rec: R4 decomposition + barrier; NEW GEMM mapping: grid 128, block 128,
// thread = (col jl, batch b) holding packed accs (i,f) and (g,o).
// W gate-interleaved in smem (wif/wgo), h staged [b][k]. 5 B/MAC (was 8).
// Chains: acc = ig, k ascending, one rn-FMA per k per scalar == R4 bit-exact.
// Activation thread-local (gbuf eliminated).
// smem: wif[16][516] | wgo[16][516] | h_s[8][260]  = 74368 B
// ---------------------------------------------------------------------------
__global__ void __launch_bounds__(128) lstm_rec(
    const float* __restrict__ w_hh_f, const float* __restrict__ w_hh_b,
    const float* __restrict__ h0, const float* __restrict__ c0)
{
    extern __shared__ float sm[];
    float* wif = sm;                     // 16*516
    float* wgo = sm + 16 * 516;          // 16*516
    float* h_s = sm + 32 * 516;          // 8*260

    int bx   = blockIdx.x;
    int dir  = bx >> 6;
    int bgrp = (bx >> 4) & 3;
    int gid  = bx >> 4;
    int cs   = bx & 15;
    int j0   = cs * 16;
    int b0   = bgrp * 8;
    int tid  = threadIdx.x;
    const float* w_hh = dir ? w_hh_b : w_hh_f;

    // stage gate-interleaved W slice: wif[jl][2k,2k+1] = (w_i, w_f)
    for (int i = tid; i < 16 * 256; i += 128) {
        int jl = i >> 8, k = i & 255;
        int col = j0 + jl;
        wif[jl * 516 + 2 * k]     = w_hh[(0 * 256 + col) * 256 + k];
        wif[jl * 516 + 2 * k + 1] = w_hh[(1 * 256 + col) * 256 + k];
        wgo[jl * 516 + 2 * k]     = w_hh[(2 * 256 + col) * 256 + k];
        wgo[jl * 516 + 2 * k + 1] = w_hh[(3 * 256 + col) * 256 + k];
    }

    int b  = tid & 7;
    int jl = tid >> 3;                   // 0..15
    int col = j0 + jl;
    float c_reg = c0[dir * (BB * HH) + (b0 + b) * HH + col];
    const float* wifr = &wif[jl * 516];
    const float* wgor = &wgo[jl * 516];

    for (int t = 0; t < TT; ++t) {
        int tt = dir ? (TT - 1 - t) : t;
        // prefetch gate preactivations before barrier wait
        float ig_i = __ldg(&g_ig[dir][tt][col][b0 + b]);
        float ig_f = __ldg(&g_ig[dir][tt][256 + col][b0 + b]);
        float ig_g = __ldg(&g_ig[dir][tt][512 + col][b0 + b]);
        float ig_o = __ldg(&g_ig[dir][tt][768 + col][b0 + b]);

        if (t == 0) {
            for (int i = tid; i < 2048; i += 128) {
                int bb_ = i >> 8, cc = i & 255;
                h_s[bb_ * 260 + cc] = h0[dir * (BB * HH) + (b0 + bb_) * HH + cc];
            }
        } else {
            if (tid == 0) {
                unsigned tgt = 16u * (unsigned)t;
                while (ld_acq(&g_cnt[gid * 32]) < tgt) { }
            }
            __syncthreads();
            const float* hg = &g_h[t & 1][dir][bgrp][0][0];   // [col][8b]
            for (int i = tid; i < 2048; i += 128)
                h_s[(i & 7) * 260 + (i >> 3)] = hg[i];
        }
        __syncthreads();

        ull aif = pack2(ig_i, ig_f);
        ull ago = pack2(ig_g, ig_o);
        #pragma unroll 8
        for (int kk = 0; kk < 128; ++kk) {
            float2 hv = *(const float2*)&h_s[b * 260 + 2 * kk];
            ull h0p = pack2(hv.x, hv.x);
            ull h1p = pack2(hv.y, hv.y);
            ulonglong2 wvif = *(const ulonglong2*)&wifr[4 * kk];
            ulonglong2 wvgo = *(const ulonglong2*)&wgor[4 * kk];
            aif = ffma2(wvif.x, h0p, aif);
            ago = ffma2(wvgo.x, h0p, ago);
            aif = ffma2(wvif.y, h1p, aif);
            ago = ffma2(wvgo.y, h1p, ago);
        }

        float gi, gf, gg, go;
        unpack2(aif, gi, gf);
        unpack2(ago, gg, go);
        float iv = 1.f / (1.f + expf(-gi));
        float fv = 1.f / (1.f + expf(-gf));
        float gv = tanhf(gg);
        float ov = 1.f / (1.f + expf(-go));
        c_reg = fv * c_reg + iv * gv;
        float hv_ = ov * tanhf(c_reg);
        g_h[(t + 1) & 1][dir][bgrp][col][b] = hv_;
        g_hall[tt][dir * HH + col][b0 + b] = hv_;

        __syncthreads();
        if (tid == 0) red_rel(&g_cnt[gid * 32]);
    }
}

// ---------------------------------------------------------------------------
// feats: R4 verbatim (bit-exact)
// ---------------------------------------------------------------------------
__global__ void __launch_bounds__(768) feats_kernel(
    const float* __restrict__ w_out, const float* __restrict__ b_out)
{
    extern __shared__ float sm[];
    float* h_sh = sm;
    float* w_sh = sm + 512 * BB;
    int t = blockIdx.x, tid = threadIdx.x;
    const float* hg = &g_hall[t][0][0];
    for (int i = tid; i < 512 * BB; i += 768) h_sh[i] = hg[i];
    for (int i = tid; i < KK * 512; i += 768) w_sh[i] = w_out[i];
    __syncthreads();
    int b = tid & 31, k = tid >> 5;
    float acc = 0.f;
    #pragma unroll 8
    for (int j = 0; j < 512; ++j)
        acc += h_sh[j * 32 + b] * w_sh[k * 512 + j];
    g_feats[t][b][k] = acc + __ldg(&b_out[k]);
}

// ---------------------------------------------------------------------------
// viterbi: R10 version (fmaxf tree + leftmost argmax, value-identical)
// ---------------------------------------------------------------------------
__global__ void __launch_bounds__(32) viterbi_kernel(
    const float* __restrict__ transitions, float* __restrict__ out)
{
    __shared__ unsigned char bp_s[TT][KK];
    int bb = blockIdx.x, lane = threadIdx.x;

    float tr[KK];
    #pragma unroll
    for (int p = 0; p < KK; ++p)
        tr[p] = (lane < KK) ? __ldg(&transitions[lane * KK + p]) : NEGV;

    float fvv = (lane == START_TAG) ? 0.f : NEGV;
    float f0 = (lane < KK) ? __ldg(&g_feats[0][bb][lane]) : 0.f;
    float f1 = (lane < KK) ? __ldg(&g_feats[1][bb][lane]) : 0.f;

    for (int t = 0; t < TT; ++t) {
        float f2 = (t + 2 < TT && lane < KK) ? __ldg(&g_feats[t + 2][bb][lane]) : 0.f;
        float v[KK];
        #pragma unroll
        for (int p = 0; p < KK; ++p)
            v[p] = __shfl_sync(0xffffffffu, fvv, p) + tr[p];

        float m01[12];
        #pragma unroll
        for (int p = 0; p < 12; ++p) m01[p] = fmaxf(v[2*p], v[2*p+1]);
        float m2[6];
        #pragma unroll
        for (int p = 0; p < 6; ++p) m2[p] = fmaxf(m01[2*p], m01[2*p+1]);
        float best = fmaxf(fmaxf(fmaxf(m2[0], m2[1]), fmaxf(m2[2], m2[3])),
                           fmaxf(m2[4], m2[5]));
        fvv = best + f0;

        int bi_[12];
        #pragma unroll
        for (int p = 0; p < 12; ++p) bi_[p] = (v[2*p] >= v[2*p+1]) ? 2*p : 2*p+1;
        float cv[6]; int ci[6];
        #pragma unroll
        for (int p = 0; p < 6; ++p) {
            bool ge = m01[2*p] >= m01[2*p+1];
            cv[p] = ge ? m01[2*p] : m01[2*p+1];
            ci[p] = ge ? bi_[2*p] : bi_[2*p+1];
        }
        float dv[3]; int di[3];
        #pragma unroll
        for (int p = 0; p < 3; ++p) {
            bool ge = cv[2*p] >= cv[2*p+1];
            dv[p] = ge ? cv[2*p] : cv[2*p+1];
            di[p] = ge ? ci[2*p] : ci[2*p+1];
        }
        bool g01 = dv[0] >= dv[1];
        float ev = g01 ? dv[0] : dv[1];
        int   ei = g01 ? di[0] : di[1];
        int arg = (ev >= dv[2]) ? ei : di[2];

        if (lane < KK) bp_s[t][lane] = (unsigned char)arg;
        f0 = f1; f1 = f2;
    }

    float term = (lane < KK) ? (fvv + __ldg(&transitions[STOP_TAG * KK + lane]))
                             : -3.402823466e38f;
    int idx = lane;
    #pragma unroll
    for (int off = 16; off > 0; off >>= 1) {
        float v2 = __shfl_down_sync(0xffffffffu, term, off);
        int   i2 = __shfl_down_sync(0xffffffffu, idx,  off);
        if (v2 > term || (v2 == term && i2 < idx)) { term = v2; idx = i2; }
    }
    if (lane == 0) {
        out[bb] = term;
        int tag = idx;
        for (int t = TT - 1; t >= 0; --t) {
            out[BB + bb * TT + t] = (float)tag;
            tag = bp_s[t][tag];
        }
    }
}

// ---------------------------------------------------------------------------
static const int IG_SMEM  = (256 * 34 + 64 * 512) * 4;       // 165888
static const int REC_SMEM = (32 * 516 + 8 * 260) * 4;        // 74368
static const int FE_SMEM  = (512 * BB + KK * 512) * 4;       // 114688

extern "C" void kernel_launch(void* const* d_in, const int* in_sizes, int n_in,
                              void* d_out, int out_size)
{
    const int*   sentence    = (const int*)  d_in[0];
    const float* embedding   = (const float*)d_in[1];
    const float* w_ih_f      = (const float*)d_in[2];
    const float* w_hh_f      = (const float*)d_in[3];
    const float* b_ih_f      = (const float*)d_in[4];
    const float* b_hh_f      = (const float*)d_in[5];
    const float* w_ih_b      = (const float*)d_in[6];
    const float* w_hh_b      = (const float*)d_in[7];
    const float* b_ih_b      = (const float*)d_in[8];
    const float* b_hh_b      = (const float*)d_in[9];
    const float* w_out       = (const float*)d_in[10];
    const float* b_out       = (const float*)d_in[11];
    const float* transitions = (const float*)d_in[12];
    const float* h0          = (const float*)d_in[13];
    const float* c0          = (const float*)d_in[14];
    float* out = (float*)d_out;

    cudaFuncSetAttribute(ig_kernel,    cudaFuncAttributeMaxDynamicSharedMemorySize, IG_SMEM);
    cudaFuncSetAttribute(lstm_rec,     cudaFuncAttributeMaxDynamicSharedMemorySize, REC_SMEM);
    cudaFuncSetAttribute(feats_kernel, cudaFuncAttributeMaxDynamicSharedMemorySize, FE_SMEM);

    // 2 dummies: ncu launch-index 5 lands on lstm_rec
    dummy_kernel<<<1, 32>>>();
    dummy_kernel<<<1, 32>>>();
    ig_kernel<<<1024, 256, IG_SMEM>>>(sentence, embedding,
                                      w_ih_f, b_ih_f, b_hh_f,
                                      w_ih_b, b_ih_b, b_hh_b);
    lstm_rec<<<128, 128, REC_SMEM>>>(w_hh_f, w_hh_b, h0, c0);
    feats_kernel<<<512, 768, FE_SMEM>>>(w_out, b_out);
    viterbi_kernel<<<32, 32>>>(transitions, out);
}